// round 8
// baseline (speedup 1.0000x reference)
#include <cuda_runtime.h>
#include <cuda_bf16.h>
#include <math.h>
#include <stdint.h>

// ---------------------------------------------------------------------------
// CircleLoss forward, B=8192, D=1024, N_IDS=512 — mma.sync bf16 edition, v2.
//  1) normalize (fp32) -> bf16 matrix g_xb
//  2) triangular 128x128-tile HMMA GEMM, 3-stage cp.async pipeline; epilogue
//     accumulates exp(relu(s+.25)(s-.25)*64 - 60) for every DIFFERENT-target
//     pair (exact neg_mask, fixed-max LSE valid for all s in [-1,1]);
//     row partials + mirrored col partials (deterministic).
//  3) pos_k: per row, same-target sims via fp32 dots of bf16 inputs -> exact
//     lse_p (deterministic fixed-order sum).
//  4) combine: loss = softplus(60 + log(sum_neg) + lse_p); mean over valid.
// ---------------------------------------------------------------------------

#define NB 8192
#define ND 1024
#define NT 64               // 8192 / 128 tiles
#define STAGE_BYTES 10240u  // 128 rows * 80 B (40 halves, padded)

__device__ __nv_bfloat16 g_xb[NB * ND];     // 16 MB (L2-resident)
__device__ float g_part_n[NB * NT];         // 2 MB
__device__ float g_lsep[NB];
__device__ float g_loss[NB];
__device__ int   g_valid[NB];
__device__ int   g_tgt[NB];
__device__ int   g_hist[512];
__device__ int   g_goff[512];
__device__ int   g_members[NB];
__device__ int   g_is64;

// ---------------- PTX helpers ----------------------------------------------
__device__ __forceinline__ uint32_t smem_u32(const void* p) {
    uint32_t a;
    asm("{ .reg .u64 t; cvta.to.shared.u64 t, %1; cvt.u32.u64 %0, t; }"
        : "=r"(a) : "l"(p));
    return a;
}
__device__ __forceinline__ void cp16(uint32_t dst, const void* src) {
    asm volatile("cp.async.cg.shared.global [%0], [%1], 16;"
                 :: "r"(dst), "l"(src) : "memory");
}
#define CP_COMMIT() asm volatile("cp.async.commit_group;" ::: "memory")
#define CP_WAIT(n)  asm volatile("cp.async.wait_group %0;" :: "n"(n) : "memory")

__device__ __forceinline__ void ldm_x4(uint32_t a, uint32_t& r0, uint32_t& r1,
                                       uint32_t& r2, uint32_t& r3) {
    asm volatile("ldmatrix.sync.aligned.m8n8.x4.shared.b16 {%0,%1,%2,%3}, [%4];"
                 : "=r"(r0), "=r"(r1), "=r"(r2), "=r"(r3) : "r"(a));
}
__device__ __forceinline__ void ldm_x2(uint32_t a, uint32_t& r0, uint32_t& r1) {
    asm volatile("ldmatrix.sync.aligned.m8n8.x2.shared.b16 {%0,%1}, [%2];"
                 : "=r"(r0), "=r"(r1) : "r"(a));
}
__device__ __forceinline__ void mma16816(float* d, const uint32_t* a,
                                         const uint32_t* b) {
    asm volatile(
        "mma.sync.aligned.m16n8k16.row.col.f32.bf16.bf16.f32 "
        "{%0,%1,%2,%3}, {%4,%5,%6,%7}, {%8,%9}, {%0,%1,%2,%3};"
        : "+f"(d[0]), "+f"(d[1]), "+f"(d[2]), "+f"(d[3])
        : "r"(a[0]), "r"(a[1]), "r"(a[2]), "r"(a[3]), "r"(b[0]), "r"(b[1]));
}

// ---------------------------------------------------------------------------
// Kernel 0: zero histogram; detect targets dtype (int64 LE has odd words 0).
// ---------------------------------------------------------------------------
__global__ void detect_k(const int* __restrict__ tg32) {
    int tid = threadIdx.x;
    if (tid < 512) g_hist[tid] = 0;
    if (tid == 0) {
        int odd_or = 0;
        #pragma unroll
        for (int i = 1; i < 128; i += 2) odd_or |= tg32[i];
        g_is64 = (odd_or == 0) ? 1 : 0;
    }
}

// ---------------------------------------------------------------------------
// Kernel 1: fp32 normalize -> bf16; targets -> int32; histogram.
// ---------------------------------------------------------------------------
__global__ __launch_bounds__(256) void normalize_k(const float* __restrict__ x,
                                                   const void* __restrict__ tg) {
    int row = blockIdx.x;
    int tid = threadIdx.x;
    float4 v = reinterpret_cast<const float4*>(x)[row * (ND / 4) + tid];
    float ss = v.x * v.x + v.y * v.y + v.z * v.z + v.w * v.w;
    #pragma unroll
    for (int o = 16; o; o >>= 1) ss += __shfl_xor_sync(0xffffffffu, ss, o);
    __shared__ float sh[8];
    if ((tid & 31) == 0) sh[tid >> 5] = ss;
    __syncthreads();
    if (tid < 32) {
        float t = (tid < 8) ? sh[tid] : 0.f;
        #pragma unroll
        for (int o = 4; o; o >>= 1) t += __shfl_xor_sync(0xffffffffu, t, o);
        if (tid == 0) sh[0] = t;
    }
    __syncthreads();
    float inv = 1.0f / fmaxf(sqrtf(sh[0]), 1e-12f);
    __nv_bfloat162 p0 = __floats2bfloat162_rn(v.x * inv, v.y * inv);
    __nv_bfloat162 p1 = __floats2bfloat162_rn(v.z * inv, v.w * inv);
    __nv_bfloat162* dst =
        reinterpret_cast<__nv_bfloat162*>(g_xb + (size_t)row * ND + tid * 4);
    dst[0] = p0; dst[1] = p1;
    if (tid == 0) {
        int t = g_is64 ? (int)((const long long*)tg)[row]
                       : ((const int*)tg)[row];
        g_tgt[row] = t;
        if ((unsigned)t < 512u) atomicAdd(&g_hist[t], 1);
    }
}

// ---------------------------------------------------------------------------
// Kernel 2: exclusive prefix sum of histogram.
// ---------------------------------------------------------------------------
__global__ void prefix_k() {
    __shared__ int sh[512];
    int t = threadIdx.x;
    sh[t] = g_hist[t];
    __syncthreads();
    for (int off = 1; off < 512; off <<= 1) {
        int v = (t >= off) ? sh[t - off] : 0;
        __syncthreads();
        sh[t] += v;
        __syncthreads();
    }
    g_goff[t] = sh[t] - g_hist[t];
}

// ---------------------------------------------------------------------------
// Kernel 3: group member lists — one WARP per target, pure warp-sync ballot
// scan, ascending row order (deterministic), zero block barriers.
// ---------------------------------------------------------------------------
__global__ __launch_bounds__(256) void members_k() {
    int gw = (blockIdx.x * 256 + threadIdx.x) >> 5;  // global warp = target id
    int lane = threadIdx.x & 31;
    int pos = g_goff[gw];
    for (int base = 0; base < NB; base += 32) {
        int r = g_tgt[base + lane];
        unsigned bal = __ballot_sync(0xffffffffu, r == gw);
        if (r == gw)
            g_members[pos + __popc(bal & ((1u << lane) - 1u))] = base + lane;
        pos += __popc(bal);
    }
}

// ---------------------------------------------------------------------------
// Kernel 4: HMMA triangular GEMM + negative-LSE epilogue.
// CTA tile 128x128, 8 warps (2x4), warp tile 64x32, BK=32, 3-stage cp.async
// pipeline (dynamic smem 61440 B), ONE barrier per k-iteration.
// Epilogue zeroes same-target pairs exactly (== reference neg_mask).
// ---------------------------------------------------------------------------
__global__ __launch_bounds__(256) void gemm_k() {
    int bx = blockIdx.x, by = blockIdx.y;
    if (bx < by) return;
    const int rm = by * 128, cn = bx * 128;

    extern __shared__ char smem[];
    __shared__ int sh_tr[128], sh_tc[128];

    int tid = threadIdx.x, lane = tid & 31, wid = tid >> 5;
    int warp_m = wid >> 2, warp_n = wid & 3;

    if (tid < 128) sh_tr[tid] = g_tgt[rm + tid];
    else           sh_tc[tid - 128] = g_tgt[cn + tid - 128];

    const __nv_bfloat16* gA = g_xb + (size_t)rm * ND;
    const __nv_bfloat16* gB = g_xb + (size_t)cn * ND;
    uint32_t aSm = smem_u32(smem);                       // A stages: 3 * 10240
    uint32_t bSm = aSm + 3 * STAGE_BYTES;                // B stages: 3 * 10240

    // copy lanes: 512 16B-chunks per tile, 2 per thread
    int ch0 = tid * 2, ch1 = tid * 2 + 1;
    int cr0 = ch0 >> 2, cs0 = ch0 & 3, cr1 = ch1 >> 2, cs1 = ch1 & 3;
    uint32_t oA0 = (uint32_t)(cr0 * 80 + cs0 * 16), oA1 = (uint32_t)(cr1 * 80 + cs1 * 16);
    const __nv_bfloat16* pA0 = gA + (size_t)cr0 * ND + cs0 * 8;
    const __nv_bfloat16* pA1 = gA + (size_t)cr1 * ND + cs1 * 8;
    const __nv_bfloat16* pB0 = gB + (size_t)cr0 * ND + cs0 * 8;
    const __nv_bfloat16* pB1 = gB + (size_t)cr1 * ND + cs1 * 8;

    float acc[4][4][4];
    #pragma unroll
    for (int i = 0; i < 4; i++)
        #pragma unroll
        for (int j = 0; j < 4; j++)
            #pragma unroll
            for (int e = 0; e < 4; e++) acc[i][j][e] = 0.f;

    uint32_t aF = aSm + ((warp_m * 64 + (lane & 15)) * 40 + (lane >> 4) * 8) * 2;
    uint32_t bF = bSm + ((warp_n * 32 + ((lane & 15) & 7)) * 40 +
                         (((lane & 15) >> 3)) * 8) * 2;

    // prefetch stages 0, 1
    #pragma unroll
    for (int s = 0; s < 2; s++) {
        uint32_t so = s * STAGE_BYTES;
        cp16(aSm + so + oA0, pA0 + s * 32);
        cp16(aSm + so + oA1, pA1 + s * 32);
        cp16(bSm + so + oA0, pB0 + s * 32);
        cp16(bSm + so + oA1, pB1 + s * 32);
        CP_COMMIT();
    }

    int sc = 0;  // kc % 3
    for (int kc = 0; kc < 32; kc++) {
        if (kc < 30) { CP_WAIT(1); } else { CP_WAIT(0); }
        __syncthreads();
        if (kc + 2 < 32) {
            int sn = sc + 2; if (sn >= 3) sn -= 3;
            uint32_t so = (uint32_t)sn * STAGE_BYTES;
            const __nv_bfloat16* qa = pA0 + (kc + 2) * 32;
            cp16(aSm + so + oA0, qa);
            cp16(aSm + so + oA1, pA1 + (kc + 2) * 32);
            cp16(bSm + so + oA0, pB0 + (kc + 2) * 32);
            cp16(bSm + so + oA1, pB1 + (kc + 2) * 32);
            CP_COMMIT();
        }
        uint32_t bo = (uint32_t)sc * STAGE_BYTES;
        #pragma unroll
        for (int kk = 0; kk < 2; kk++) {
            uint32_t af[4][4], bf2[4][2];
            #pragma unroll
            for (int am = 0; am < 4; am++)
                ldm_x4(aF + bo + am * 1280u + kk * 32u,
                       af[am][0], af[am][1], af[am][2], af[am][3]);
            #pragma unroll
            for (int an = 0; an < 4; an++)
                ldm_x2(bF + bo + an * 640u + kk * 32u, bf2[an][0], bf2[an][1]);
            #pragma unroll
            for (int am = 0; am < 4; am++)
                #pragma unroll
                for (int an = 0; an < 4; an++)
                    mma16816(acc[am][an], af[am], bf2[an]);
        }
        if (++sc == 3) sc = 0;
    }
    __syncthreads();   // all ldmatrix done before smem reuse below

    // ---- epilogue: different-target exp sums (exact neg_mask) ------------
    float rsum[4][2];
    float csum[4][2];
    #pragma unroll
    for (int a = 0; a < 4; a++) {
        rsum[a][0] = rsum[a][1] = 0.f;
        csum[a][0] = csum[a][1] = 0.f;
    }
    int lr_base = warp_m * 64;
    int lc_base = warp_n * 32;
    #pragma unroll
    for (int am = 0; am < 4; am++) {
        int r0 = lr_base + am * 16 + (lane >> 2);
        #pragma unroll
        for (int an = 0; an < 4; an++) {
            int c0 = lc_base + an * 8 + (lane & 3) * 2;
            #pragma unroll
            for (int e = 0; e < 4; e++) {
                int r = r0 + (e >> 1) * 8;
                int c = c0 + (e & 1);
                float s = acc[am][an][e];
                float ex = __expf(fmaxf(s + 0.25f, 0.f) * (s - 0.25f) * 64.f - 60.f);
                if (sh_tr[r] == sh_tc[c]) ex = 0.f;   // same-target: not a negative
                rsum[am][e >> 1] += ex;
                csum[an][e & 1] += ex;
            }
        }
    }

    float* rowbuf = reinterpret_cast<float*>(smem);      // [4][128]
    float* colbuf = rowbuf + 512;                        // [2][128]

    #pragma unroll
    for (int am = 0; am < 4; am++)
        #pragma unroll
        for (int t = 0; t < 2; t++) {
            float v = rsum[am][t];
            v += __shfl_xor_sync(0xffffffffu, v, 1);
            v += __shfl_xor_sync(0xffffffffu, v, 2);
            if ((lane & 3) == 0)
                rowbuf[warp_n * 128 + lr_base + am * 16 + t * 8 + (lane >> 2)] = v;
        }
    #pragma unroll
    for (int an = 0; an < 4; an++)
        #pragma unroll
        for (int c = 0; c < 2; c++) {
            float v = csum[an][c];
            v += __shfl_xor_sync(0xffffffffu, v, 4);
            v += __shfl_xor_sync(0xffffffffu, v, 8);
            v += __shfl_xor_sync(0xffffffffu, v, 16);
            if (lane < 4)
                colbuf[warp_m * 128 + lc_base + an * 8 + lane * 2 + c] = v;
        }
    __syncthreads();
    if (tid < 128) {
        float s = rowbuf[tid] + rowbuf[128 + tid] + rowbuf[256 + tid] + rowbuf[384 + tid];
        g_part_n[(size_t)(rm + tid) * NT + bx] = s;
        if (bx > by) {
            float cs2 = colbuf[tid] + colbuf[128 + tid];
            g_part_n[(size_t)(cn + tid) * NT + by] = cs2;
        }
    }
}

// ---------------------------------------------------------------------------
// Kernel 5: positives. One block (256 thr) per row; warps stride over group
// members (fp32 dots of bf16 inputs); exact lse_p, deterministic order.
// ---------------------------------------------------------------------------
__global__ __launch_bounds__(256) void pos_k() {
    int i = blockIdx.x;
    int tid = threadIdx.x, wid = tid >> 5, lane = tid & 31;
    __shared__ float lp_list[512];

    int t = g_tgt[i];
    int cnt = ((unsigned)t < 512u) ? g_hist[t] : 0;
    if (cnt < 2 || cnt >= NB) {
        if (tid == 0) { g_lsep[i] = 0.f; g_valid[i] = 0; }
        return;
    }
    int nmax = cnt > 512 ? 512 : cnt;

    // this row's 32 halves per lane
    float xi[32];
    {
        const uint4* p = reinterpret_cast<const uint4*>(g_xb + (size_t)i * ND + lane * 32);
        #pragma unroll
        for (int q = 0; q < 4; q++) {
            uint4 u = p[q];
            const __nv_bfloat162* h = reinterpret_cast<const __nv_bfloat162*>(&u);
            #pragma unroll
            for (int e = 0; e < 4; e++) {
                float2 f = __bfloat1622float2(h[e]);
                xi[q * 8 + e * 2] = f.x; xi[q * 8 + e * 2 + 1] = f.y;
            }
        }
    }
    int off = g_goff[t];
    for (int jj = wid; jj < nmax; jj += 8) {
        int j = g_members[off + jj];
        float lp = -1e30f;
        if (j != i) {
            const uint4* p = reinterpret_cast<const uint4*>(g_xb + (size_t)j * ND + lane * 32);
            float acc = 0.f;
            #pragma unroll
            for (int q = 0; q < 4; q++) {
                uint4 u = p[q];
                const __nv_bfloat162* h = reinterpret_cast<const __nv_bfloat162*>(&u);
                #pragma unroll
                for (int e = 0; e < 4; e++) {
                    float2 f = __bfloat1622float2(h[e]);
                    acc = fmaf(xi[q * 8 + e * 2], f.x, acc);
                    acc = fmaf(xi[q * 8 + e * 2 + 1], f.y, acc);
                }
            }
            #pragma unroll
            for (int o = 16; o; o >>= 1) acc += __shfl_xor_sync(0xffffffffu, acc, o);
            lp = -fmaxf(1.25f - acc, 0.f) * (acc - 0.75f) * 64.f;
        }
        if (lane == 0) lp_list[jj] = lp;
    }
    __syncthreads();
    if (tid == 0) {
        float m = -1e30f;
        for (int a = 0; a < nmax; a++) m = fmaxf(m, lp_list[a]);
        float ssum = 0.f;
        for (int a = 0; a < nmax; a++) ssum += __expf(lp_list[a] - m);
        g_lsep[i] = m + logf(ssum);
        g_valid[i] = 1;
    }
}

// ---------------------------------------------------------------------------
// Kernel 6: per-row combine, softplus.
// ---------------------------------------------------------------------------
__global__ __launch_bounds__(256) void rowlse_k() {
    int row = blockIdx.x * 256 + threadIdx.x;
    float sn = 0.f;
    #pragma unroll 16
    for (int k = 0; k < NT; k++) sn += g_part_n[(size_t)row * NT + k];
    float loss = 0.f;
    if (g_valid[row]) {
        sn = fmaxf(sn, 1e-37f);
        float x = 60.f + logf(sn) + g_lsep[row];
        loss = fmaxf(x, 0.f) + log1pf(expf(-fabsf(x)));
    }
    g_loss[row] = loss;
}

// ---------------------------------------------------------------------------
// Kernel 7: deterministic final reduction.
// ---------------------------------------------------------------------------
__global__ __launch_bounds__(1024) void finalize_k(float* __restrict__ out) {
    __shared__ float sh_s[1024];
    __shared__ int sh_c[1024];
    int tid = threadIdx.x;
    float t = 0.f;
    int c = 0;
    for (int r = tid; r < NB; r += 1024) {
        t += g_loss[r];
        c += g_valid[r];
    }
    sh_s[tid] = t; sh_c[tid] = c;
    __syncthreads();
    for (int off = 512; off > 0; off >>= 1) {
        if (tid < off) {
            sh_s[tid] += sh_s[tid + off];
            sh_c[tid] += sh_c[tid + off];
        }
        __syncthreads();
    }
    if (tid == 0) {
        int cnt = sh_c[0] > 1 ? sh_c[0] : 1;
        out[0] = sh_s[0] / (float)cnt;
    }
}

// ---------------------------------------------------------------------------
extern "C" void kernel_launch(void* const* d_in, const int* in_sizes, int n_in,
                              void* d_out, int out_size) {
    const float* x = (const float*)d_in[0];
    const void* tg = d_in[1];
    float* out = (float*)d_out;

    cudaFuncSetAttribute(gemm_k, cudaFuncAttributeMaxDynamicSharedMemorySize, 61440);

    detect_k<<<1, 512>>>((const int*)tg);
    normalize_k<<<NB, 256>>>(x, tg);
    prefix_k<<<1, 512>>>();
    members_k<<<64, 256>>>();
    gemm_k<<<dim3(NT, NT), 256, 61440>>>();
    pos_k<<<NB, 256>>>();
    rowlse_k<<<NB / 256, 256>>>();
    finalize_k<<<1, 1024>>>(out);
}

// round 9
// speedup vs baseline: 1.1121x; 1.1121x over previous
#include <cuda_runtime.h>
#include <cuda_bf16.h>
#include <math.h>
#include <stdint.h>

// ---------------------------------------------------------------------------
// CircleLoss forward, B=8192, D=1024, N_IDS=512 — mma.sync bf16 edition, v3.
//  1) normalize (fp32) -> bf16 matrix g_xb
//  2) triangular 128x128-tile HMMA GEMM (1-D triangular grid), 3-stage
//     cp.async pipeline; epilogue accumulates exp(relu(s+.25)(s-.25)*64 - 60)
//     for every DIFFERENT-target pair (exact neg_mask; fixed-max LSE valid
//     for all s in [-1,1]); row partials + mirrored col partials.
//  3) pos_k: per row, same-target sims via fp32 dots of bf16 inputs -> exact
//     lse_p (deterministic fixed-order sum).
//  4) combine: loss = softplus(60 + log(sum_neg) + lse_p); mean over valid.
// ---------------------------------------------------------------------------

#define NB 8192
#define ND 1024
#define NT 64               // 8192 / 128 tiles
#define NTRI (NT * (NT + 1) / 2)   // 2080 triangular tiles
#define STAGE_BYTES 10240u  // 128 rows * 80 B (40 halves, padded)

__device__ __nv_bfloat16 g_xb[NB * ND];     // 16 MB (L2-resident)
__device__ float g_part_n[NB * NT];         // 2 MB
__device__ float g_lsep[NB];
__device__ float g_loss[NB];
__device__ int   g_valid[NB];
__device__ int   g_tgt[NB];
__device__ int   g_hist[512];
__device__ int   g_goff[512];
__device__ int   g_members[NB];
__device__ int   g_is64;

// ---------------- PTX helpers ----------------------------------------------
__device__ __forceinline__ uint32_t smem_u32(const void* p) {
    uint32_t a;
    asm("{ .reg .u64 t; cvta.to.shared.u64 t, %1; cvt.u32.u64 %0, t; }"
        : "=r"(a) : "l"(p));
    return a;
}
__device__ __forceinline__ void cp16(uint32_t dst, const void* src) {
    asm volatile("cp.async.cg.shared.global [%0], [%1], 16;"
                 :: "r"(dst), "l"(src) : "memory");
}
#define CP_COMMIT() asm volatile("cp.async.commit_group;" ::: "memory")
#define CP_WAIT(n)  asm volatile("cp.async.wait_group %0;" :: "n"(n) : "memory")

__device__ __forceinline__ void ldm_x4(uint32_t a, uint32_t& r0, uint32_t& r1,
                                       uint32_t& r2, uint32_t& r3) {
    asm volatile("ldmatrix.sync.aligned.m8n8.x4.shared.b16 {%0,%1,%2,%3}, [%4];"
                 : "=r"(r0), "=r"(r1), "=r"(r2), "=r"(r3) : "r"(a));
}
__device__ __forceinline__ void ldm_x2(uint32_t a, uint32_t& r0, uint32_t& r1) {
    asm volatile("ldmatrix.sync.aligned.m8n8.x2.shared.b16 {%0,%1}, [%2];"
                 : "=r"(r0), "=r"(r1) : "r"(a));
}
__device__ __forceinline__ void mma16816(float* d, const uint32_t* a,
                                         const uint32_t* b) {
    asm volatile(
        "mma.sync.aligned.m16n8k16.row.col.f32.bf16.bf16.f32 "
        "{%0,%1,%2,%3}, {%4,%5,%6,%7}, {%8,%9}, {%0,%1,%2,%3};"
        : "+f"(d[0]), "+f"(d[1]), "+f"(d[2]), "+f"(d[3])
        : "r"(a[0]), "r"(a[1]), "r"(a[2]), "r"(a[3]), "r"(b[0]), "r"(b[1]));
}

// ---------------------------------------------------------------------------
// Kernel 0: zero histogram; detect targets dtype (int64 LE has odd words 0).
// ---------------------------------------------------------------------------
__global__ void detect_k(const int* __restrict__ tg32) {
    int tid = threadIdx.x;
    if (tid < 512) g_hist[tid] = 0;
    if (tid == 0) {
        int odd_or = 0;
        #pragma unroll
        for (int i = 1; i < 128; i += 2) odd_or |= tg32[i];
        g_is64 = (odd_or == 0) ? 1 : 0;
    }
}

// ---------------------------------------------------------------------------
// Kernel 1: fp32 normalize -> bf16; targets -> int32; histogram.
// ---------------------------------------------------------------------------
__global__ __launch_bounds__(256) void normalize_k(const float* __restrict__ x,
                                                   const void* __restrict__ tg) {
    int row = blockIdx.x;
    int tid = threadIdx.x;
    float4 v = reinterpret_cast<const float4*>(x)[row * (ND / 4) + tid];
    float ss = v.x * v.x + v.y * v.y + v.z * v.z + v.w * v.w;
    #pragma unroll
    for (int o = 16; o; o >>= 1) ss += __shfl_xor_sync(0xffffffffu, ss, o);
    __shared__ float sh[8];
    if ((tid & 31) == 0) sh[tid >> 5] = ss;
    __syncthreads();
    if (tid < 32) {
        float t = (tid < 8) ? sh[tid] : 0.f;
        #pragma unroll
        for (int o = 4; o; o >>= 1) t += __shfl_xor_sync(0xffffffffu, t, o);
        if (tid == 0) sh[0] = t;
    }
    __syncthreads();
    float inv = 1.0f / fmaxf(sqrtf(sh[0]), 1e-12f);
    __nv_bfloat162 p0 = __floats2bfloat162_rn(v.x * inv, v.y * inv);
    __nv_bfloat162 p1 = __floats2bfloat162_rn(v.z * inv, v.w * inv);
    __nv_bfloat162* dst =
        reinterpret_cast<__nv_bfloat162*>(g_xb + (size_t)row * ND + tid * 4);
    dst[0] = p0; dst[1] = p1;
    if (tid == 0) {
        int t = g_is64 ? (int)((const long long*)tg)[row]
                       : ((const int*)tg)[row];
        g_tgt[row] = t;
        if ((unsigned)t < 512u) atomicAdd(&g_hist[t], 1);
    }
}

// ---------------------------------------------------------------------------
// Kernel 2: exclusive prefix sum of histogram.
// ---------------------------------------------------------------------------
__global__ void prefix_k() {
    __shared__ int sh[512];
    int t = threadIdx.x;
    sh[t] = g_hist[t];
    __syncthreads();
    for (int off = 1; off < 512; off <<= 1) {
        int v = (t >= off) ? sh[t - off] : 0;
        __syncthreads();
        sh[t] += v;
        __syncthreads();
    }
    g_goff[t] = sh[t] - g_hist[t];
}

// ---------------------------------------------------------------------------
// Kernel 3: group member lists (deterministic ballot scan). 1 block/target.
// (Reverted to the R7 block-per-target form: 21 us vs 92 us warp-per-target.)
// ---------------------------------------------------------------------------
__global__ __launch_bounds__(256) void members_k() {
    int t = blockIdx.x;
    int tid = threadIdx.x, wid = tid >> 5, lane = tid & 31;
    __shared__ int wcnt[8];
    __shared__ int sbase;
    if (tid == 0) sbase = g_goff[t];
    __syncthreads();
    for (int base = 0; base < NB; base += 256) {
        bool m = (g_tgt[base + tid] == t);
        unsigned bal = __ballot_sync(0xffffffffu, m);
        if (lane == 0) wcnt[wid] = __popc(bal);
        __syncthreads();
        if (m) {
            int woff = 0;
            for (int wdx = 0; wdx < wid; wdx++) woff += wcnt[wdx];
            g_members[sbase + woff + __popc(bal & ((1u << lane) - 1u))] = base + tid;
        }
        __syncthreads();
        if (tid == 0) {
            int tot = 0;
            for (int wdx = 0; wdx < 8; wdx++) tot += wcnt[wdx];
            sbase += tot;
        }
        __syncthreads();
    }
}

// ---------------------------------------------------------------------------
// Kernel 4: HMMA triangular GEMM + negative-LSE epilogue.
// 1-D triangular grid (2080 CTAs). CTA tile 128x128, 8 warps (2x4), warp
// tile 64x32, BK=32, 3-stage cp.async pipeline, one barrier per k-iter.
// Epilogue zeroes same-target pairs exactly (== reference neg_mask).
// ---------------------------------------------------------------------------
__device__ __forceinline__ int tri_start(int b) {  // tiles before row b
    return b * (2 * NT - b + 1) / 2;
}

__global__ __launch_bounds__(256) void gemm_k() {
    // decode 1-D triangular block id -> (by, bx), bx >= by
    int r = blockIdx.x;
    int by = (int)(NT + 0.5 - sqrt((NT + 0.5) * (NT + 0.5) - 2.0 * r));
    while (tri_start(by + 1) <= r) by++;
    while (tri_start(by) > r) by--;
    int bx = by + (r - tri_start(by));

    const int rm = by * 128, cn = bx * 128;

    extern __shared__ char smem[];
    __shared__ int sh_tr[128], sh_tc[128];

    int tid = threadIdx.x, lane = tid & 31, wid = tid >> 5;
    int warp_m = wid >> 2, warp_n = wid & 3;

    if (tid < 128) sh_tr[tid] = g_tgt[rm + tid];
    else           sh_tc[tid - 128] = g_tgt[cn + tid - 128];

    const __nv_bfloat16* gA = g_xb + (size_t)rm * ND;
    const __nv_bfloat16* gB = g_xb + (size_t)cn * ND;
    uint32_t aSm = smem_u32(smem);                       // A stages: 3 * 10240
    uint32_t bSm = aSm + 3 * STAGE_BYTES;                // B stages: 3 * 10240

    int ch0 = tid * 2, ch1 = tid * 2 + 1;
    int cr0 = ch0 >> 2, cs0 = ch0 & 3, cr1 = ch1 >> 2, cs1 = ch1 & 3;
    uint32_t oA0 = (uint32_t)(cr0 * 80 + cs0 * 16), oA1 = (uint32_t)(cr1 * 80 + cs1 * 16);
    const __nv_bfloat16* pA0 = gA + (size_t)cr0 * ND + cs0 * 8;
    const __nv_bfloat16* pA1 = gA + (size_t)cr1 * ND + cs1 * 8;
    const __nv_bfloat16* pB0 = gB + (size_t)cr0 * ND + cs0 * 8;
    const __nv_bfloat16* pB1 = gB + (size_t)cr1 * ND + cs1 * 8;

    float acc[4][4][4];
    #pragma unroll
    for (int i = 0; i < 4; i++)
        #pragma unroll
        for (int j = 0; j < 4; j++)
            #pragma unroll
            for (int e = 0; e < 4; e++) acc[i][j][e] = 0.f;

    uint32_t aF = aSm + ((warp_m * 64 + (lane & 15)) * 40 + (lane >> 4) * 8) * 2;
    uint32_t bF = bSm + ((warp_n * 32 + ((lane & 15) & 7)) * 40 +
                         (((lane & 15) >> 3)) * 8) * 2;

    #pragma unroll
    for (int s = 0; s < 2; s++) {
        uint32_t so = s * STAGE_BYTES;
        cp16(aSm + so + oA0, pA0 + s * 32);
        cp16(aSm + so + oA1, pA1 + s * 32);
        cp16(bSm + so + oA0, pB0 + s * 32);
        cp16(bSm + so + oA1, pB1 + s * 32);
        CP_COMMIT();
    }

    int sc = 0;  // kc % 3
    for (int kc = 0; kc < 32; kc++) {
        if (kc < 30) { CP_WAIT(1); } else { CP_WAIT(0); }
        __syncthreads();
        if (kc + 2 < 32) {
            int sn = sc + 2; if (sn >= 3) sn -= 3;
            uint32_t so = (uint32_t)sn * STAGE_BYTES;
            cp16(aSm + so + oA0, pA0 + (kc + 2) * 32);
            cp16(aSm + so + oA1, pA1 + (kc + 2) * 32);
            cp16(bSm + so + oA0, pB0 + (kc + 2) * 32);
            cp16(bSm + so + oA1, pB1 + (kc + 2) * 32);
            CP_COMMIT();
        }
        uint32_t bo = (uint32_t)sc * STAGE_BYTES;
        #pragma unroll
        for (int kk = 0; kk < 2; kk++) {
            uint32_t af[4][4], bf2[4][2];
            #pragma unroll
            for (int am = 0; am < 4; am++)
                ldm_x4(aF + bo + am * 1280u + kk * 32u,
                       af[am][0], af[am][1], af[am][2], af[am][3]);
            #pragma unroll
            for (int an = 0; an < 4; an++)
                ldm_x2(bF + bo + an * 640u + kk * 32u, bf2[an][0], bf2[an][1]);
            #pragma unroll
            for (int am = 0; am < 4; am++)
                #pragma unroll
                for (int an = 0; an < 4; an++)
                    mma16816(acc[am][an], af[am], bf2[an]);
        }
        if (++sc == 3) sc = 0;
    }
    __syncthreads();   // all ldmatrix done before smem reuse below

    // ---- epilogue: different-target exp sums (exact neg_mask) ------------
    float rsum[4][2];
    float csum[4][2];
    #pragma unroll
    for (int a = 0; a < 4; a++) {
        rsum[a][0] = rsum[a][1] = 0.f;
        csum[a][0] = csum[a][1] = 0.f;
    }
    int lr_base = warp_m * 64;
    int lc_base = warp_n * 32;
    #pragma unroll
    for (int am = 0; am < 4; am++) {
        int r0 = lr_base + am * 16 + (lane >> 2);
        #pragma unroll
        for (int an = 0; an < 4; an++) {
            int c0 = lc_base + an * 8 + (lane & 3) * 2;
            #pragma unroll
            for (int e = 0; e < 4; e++) {
                int rr = r0 + (e >> 1) * 8;
                int cc = c0 + (e & 1);
                float s = acc[am][an][e];
                float ex = __expf(fmaxf(s + 0.25f, 0.f) * (s - 0.25f) * 64.f - 60.f);
                if (sh_tr[rr] == sh_tc[cc]) ex = 0.f;  // same target: not a negative
                rsum[am][e >> 1] += ex;
                csum[an][e & 1] += ex;
            }
        }
    }

    float* rowbuf = reinterpret_cast<float*>(smem);      // [4][128]
    float* colbuf = rowbuf + 512;                        // [2][128]

    #pragma unroll
    for (int am = 0; am < 4; am++)
        #pragma unroll
        for (int t = 0; t < 2; t++) {
            float v = rsum[am][t];
            v += __shfl_xor_sync(0xffffffffu, v, 1);
            v += __shfl_xor_sync(0xffffffffu, v, 2);
            if ((lane & 3) == 0)
                rowbuf[warp_n * 128 + lr_base + am * 16 + t * 8 + (lane >> 2)] = v;
        }
    #pragma unroll
    for (int an = 0; an < 4; an++)
        #pragma unroll
        for (int c = 0; c < 2; c++) {
            float v = csum[an][c];
            v += __shfl_xor_sync(0xffffffffu, v, 4);
            v += __shfl_xor_sync(0xffffffffu, v, 8);
            v += __shfl_xor_sync(0xffffffffu, v, 16);
            if (lane < 4)
                colbuf[warp_m * 128 + lc_base + an * 8 + lane * 2 + c] = v;
        }
    __syncthreads();
    if (tid < 128) {
        float s = rowbuf[tid] + rowbuf[128 + tid] + rowbuf[256 + tid] + rowbuf[384 + tid];
        g_part_n[(size_t)(rm + tid) * NT + bx] = s;
        if (bx > by) {
            float cs2 = colbuf[tid] + colbuf[128 + tid];
            g_part_n[(size_t)(cn + tid) * NT + by] = cs2;
        }
    }
}

// ---------------------------------------------------------------------------
// Kernel 5: positives. One block (256 thr) per row; warps stride over group
// members (fp32 dots of bf16 inputs); exact lse_p, deterministic order.
// ---------------------------------------------------------------------------
__global__ __launch_bounds__(256) void pos_k() {
    int i = blockIdx.x;
    int tid = threadIdx.x, wid = tid >> 5, lane = tid & 31;
    __shared__ float lp_list[512];

    int t = g_tgt[i];
    int cnt = ((unsigned)t < 512u) ? g_hist[t] : 0;
    if (cnt < 2 || cnt >= NB) {
        if (tid == 0) { g_lsep[i] = 0.f; g_valid[i] = 0; }
        return;
    }
    int nmax = cnt > 512 ? 512 : cnt;

    float xi[32];
    {
        const uint4* p = reinterpret_cast<const uint4*>(g_xb + (size_t)i * ND + lane * 32);
        #pragma unroll
        for (int q = 0; q < 4; q++) {
            uint4 u = p[q];
            const __nv_bfloat162* h = reinterpret_cast<const __nv_bfloat162*>(&u);
            #pragma unroll
            for (int e = 0; e < 4; e++) {
                float2 f = __bfloat1622float2(h[e]);
                xi[q * 8 + e * 2] = f.x; xi[q * 8 + e * 2 + 1] = f.y;
            }
        }
    }
    int off = g_goff[t];
    for (int jj = wid; jj < nmax; jj += 8) {
        int j = g_members[off + jj];
        float lp = -1e30f;
        if (j != i) {
            const uint4* p = reinterpret_cast<const uint4*>(g_xb + (size_t)j * ND + lane * 32);
            float acc = 0.f;
            #pragma unroll
            for (int q = 0; q < 4; q++) {
                uint4 u = p[q];
                const __nv_bfloat162* h = reinterpret_cast<const __nv_bfloat162*>(&u);
                #pragma unroll
                for (int e = 0; e < 4; e++) {
                    float2 f = __bfloat1622float2(h[e]);
                    acc = fmaf(xi[q * 8 + e * 2], f.x, acc);
                    acc = fmaf(xi[q * 8 + e * 2 + 1], f.y, acc);
                }
            }
            #pragma unroll
            for (int o = 16; o; o >>= 1) acc += __shfl_xor_sync(0xffffffffu, acc, o);
            lp = -fmaxf(1.25f - acc, 0.f) * (acc - 0.75f) * 64.f;
        }
        if (lane == 0) lp_list[jj] = lp;
    }
    __syncthreads();
    if (tid == 0) {
        float m = -1e30f;
        for (int a = 0; a < nmax; a++) m = fmaxf(m, lp_list[a]);
        float ssum = 0.f;
        for (int a = 0; a < nmax; a++) ssum += __expf(lp_list[a] - m);
        g_lsep[i] = m + logf(ssum);
        g_valid[i] = 1;
    }
}

// ---------------------------------------------------------------------------
// Kernel 6: per-row combine, softplus.
// ---------------------------------------------------------------------------
__global__ __launch_bounds__(256) void rowlse_k() {
    int row = blockIdx.x * 256 + threadIdx.x;
    float sn = 0.f;
    #pragma unroll 16
    for (int k = 0; k < NT; k++) sn += g_part_n[(size_t)row * NT + k];
    float loss = 0.f;
    if (g_valid[row]) {
        sn = fmaxf(sn, 1e-37f);
        float x = 60.f + logf(sn) + g_lsep[row];
        loss = fmaxf(x, 0.f) + log1pf(expf(-fabsf(x)));
    }
    g_loss[row] = loss;
}

// ---------------------------------------------------------------------------
// Kernel 7: deterministic final reduction.
// ---------------------------------------------------------------------------
__global__ __launch_bounds__(1024) void finalize_k(float* __restrict__ out) {
    __shared__ float sh_s[1024];
    __shared__ int sh_c[1024];
    int tid = threadIdx.x;
    float t = 0.f;
    int c = 0;
    for (int r = tid; r < NB; r += 1024) {
        t += g_loss[r];
        c += g_valid[r];
    }
    sh_s[tid] = t; sh_c[tid] = c;
    __syncthreads();
    for (int off = 512; off > 0; off >>= 1) {
        if (tid < off) {
            sh_s[tid] += sh_s[tid + off];
            sh_c[tid] += sh_c[tid + off];
        }
        __syncthreads();
    }
    if (tid == 0) {
        int cnt = sh_c[0] > 1 ? sh_c[0] : 1;
        out[0] = sh_s[0] / (float)cnt;
    }
}

// ---------------------------------------------------------------------------
extern "C" void kernel_launch(void* const* d_in, const int* in_sizes, int n_in,
                              void* d_out, int out_size) {
    const float* x = (const float*)d_in[0];
    const void* tg = d_in[1];
    float* out = (float*)d_out;

    cudaFuncSetAttribute(gemm_k, cudaFuncAttributeMaxDynamicSharedMemorySize, 61440);

    detect_k<<<1, 512>>>((const int*)tg);
    normalize_k<<<NB, 256>>>(x, tg);
    prefix_k<<<1, 512>>>();
    members_k<<<512, 256>>>();
    gemm_k<<<NTRI, 256, 61440>>>();
    pos_k<<<NB, 256>>>();
    rowlse_k<<<NB / 256, 256>>>();
    finalize_k<<<1, 1024>>>(out);
}